// round 1
// baseline (speedup 1.0000x reference)
#include <cuda_runtime.h>
#include <cstdint>

#define Bb 2
#define Hh 48
#define Ww 48
#define DMo 192
#define Ns 16
#define DI 384
#define Rr 12
#define Kk 4
#define Ll (Hh*Ww)          // 2304
#define NCHUNK 32
#define CLEN (Ll/NCHUNK)    // 72
#define LOG2E 1.4426950408889634f

// ---------------- static device scratch (no allocations allowed) ----------------
__device__ float g_xz  [(size_t)Bb*Ll*(2*DI)];      // in_proj output (b,l,768)
__device__ float g_xc  [(size_t)Bb*Ll*DI];          // conv+silu output, channel-last (b,l,d)
__device__ float g_c44 [(size_t)Bb*Kk*Ll*44];       // x_dbl: (b,k,l,44) [0:12 dt_r | 12:28 B | 28:44 C]
__device__ float g_dts [(size_t)Bb*Kk*Ll*DI];       // dt (pre-bias, pre-softplus) (b,k,l,d)
__device__ float g_y   [(size_t)Bb*Kk*Ll*DI];       // per-direction scan output (b,k,l,d)
__device__ float g_g   [(size_t)Bb*Ll*DI];          // post-LN, gated (b,l,d)
__device__ float g_hend [(size_t)Bb*Kk*NCHUNK*DI*Ns];
__device__ float g_aprod[(size_t)Bb*Kk*NCHUNK*DI*Ns];
__device__ float g_hinit[(size_t)Bb*Kk*NCHUNK*DI*Ns];

// ---------------- helpers ----------------
__device__ __forceinline__ float ex2f(float x){ float y; asm("ex2.approx.f32 %0, %1;" : "=f"(y) : "f"(x)); return y; }

__device__ __forceinline__ float softplusf(float x){
    float e = __expf(-fabsf(x));
    return fmaxf(x, 0.f) + log1pf(e);
}

__device__ __forceinline__ float sigmoidf(float x){
    return 1.f / (1.f + __expf(-x));
}

// scan-step l of direction k reads raster location loc_of(k,l)
__device__ __forceinline__ int loc_of(int k, int l){
    int l2 = (k >= 2) ? (Ll - 1 - l) : l;
    if (k & 1){ int w = l2 / Ww; int h = l2 - w * Ww; return h * Ww + w; }
    return l2;
}

// ---------------- generic NT GEMM: C[M,N] = A[M,K] * B[N,K]^T (all row-major fp32) ----
// BM=BN=64, BK=16, 256 threads, 4x4 micro. M,N mult of 64; K mult of 16.
__device__ __forceinline__ void gemm_nt(const float* __restrict__ A, const float* __restrict__ B,
                                        float* __restrict__ C, int M, int N, int K){
    __shared__ float As[16][68];
    __shared__ float Bs[16][68];
    int t  = threadIdx.x;
    int tx = t & 15, ty = t >> 4;
    int m0 = blockIdx.y * 64, n0 = blockIdx.x * 64;
    float acc[4][4] = {};
    int r  = t >> 2;
    int kc = (t & 3) << 2;
    const float* Ap = A + (size_t)(m0 + r) * K + kc;
    const float* Bp = B + (size_t)(n0 + r) * K + kc;
    for (int k0 = 0; k0 < K; k0 += 16){
        float4 av = *(const float4*)(Ap + k0);
        float4 bv = *(const float4*)(Bp + k0);
        As[kc+0][r] = av.x; As[kc+1][r] = av.y; As[kc+2][r] = av.z; As[kc+3][r] = av.w;
        Bs[kc+0][r] = bv.x; Bs[kc+1][r] = bv.y; Bs[kc+2][r] = bv.z; Bs[kc+3][r] = bv.w;
        __syncthreads();
        #pragma unroll
        for (int kk = 0; kk < 16; kk++){
            float4 a = *(const float4*)&As[kk][ty << 2];
            float4 b = *(const float4*)&Bs[kk][tx << 2];
            acc[0][0] = fmaf(a.x, b.x, acc[0][0]); acc[0][1] = fmaf(a.x, b.y, acc[0][1]);
            acc[0][2] = fmaf(a.x, b.z, acc[0][2]); acc[0][3] = fmaf(a.x, b.w, acc[0][3]);
            acc[1][0] = fmaf(a.y, b.x, acc[1][0]); acc[1][1] = fmaf(a.y, b.y, acc[1][1]);
            acc[1][2] = fmaf(a.y, b.z, acc[1][2]); acc[1][3] = fmaf(a.y, b.w, acc[1][3]);
            acc[2][0] = fmaf(a.z, b.x, acc[2][0]); acc[2][1] = fmaf(a.z, b.y, acc[2][1]);
            acc[2][2] = fmaf(a.z, b.z, acc[2][2]); acc[2][3] = fmaf(a.z, b.w, acc[2][3]);
            acc[3][0] = fmaf(a.w, b.x, acc[3][0]); acc[3][1] = fmaf(a.w, b.y, acc[3][1]);
            acc[3][2] = fmaf(a.w, b.z, acc[3][2]); acc[3][3] = fmaf(a.w, b.w, acc[3][3]);
        }
        __syncthreads();
    }
    #pragma unroll
    for (int i = 0; i < 4; i++){
        float4 v = make_float4(acc[i][0], acc[i][1], acc[i][2], acc[i][3]);
        *(float4*)&C[(size_t)(m0 + ty*4 + i) * N + n0 + tx*4] = v;
    }
}

__global__ void k_inproj(const float* __restrict__ x, const float* __restrict__ w){
    gemm_nt(x, w, g_xz, Bb*Ll, 2*DI, DMo);
}
__global__ void k_outproj(const float* __restrict__ w, float* __restrict__ out){
    gemm_nt(g_g, w, out, Bb*Ll, DMo, DI);
}

// ---------------- depthwise conv 3x3 + bias + SiLU (channel-last) ----------------
__global__ void k_conv(const float* __restrict__ cw, const float* __restrict__ cb){
    int p = blockIdx.x % Ll;
    int b = blockIdx.x / Ll;
    int h = p / Ww, w = p % Ww;
    const float* base = g_xz + (size_t)b * Ll * (2*DI);
    #pragma unroll
    for (int j = 0; j < 3; j++){
        int d = threadIdx.x + j * 128;
        float acc = cb[d];
        const float* wr = cw + d * 9;
        #pragma unroll
        for (int dh = -1; dh <= 1; dh++){
            int hh = h + dh;
            if ((unsigned)hh >= (unsigned)Hh) continue;
            #pragma unroll
            for (int dw = -1; dw <= 1; dw++){
                int ww2 = w + dw;
                if ((unsigned)ww2 >= (unsigned)Ww) continue;
                acc = fmaf(base[(size_t)(hh*Ww + ww2) * (2*DI) + d], wr[(dh+1)*3 + (dw+1)], acc);
            }
        }
        g_xc[((size_t)b*Ll + p) * DI + d] = acc * sigmoidf(acc);
    }
}

// ---------------- x_proj (44x384 per position) + dt_proj (384x12) ----------------
// grid: (Ll/16, K, B), 128 threads. Tile of 16 scan positions.
__global__ void k_xdbl(const float* __restrict__ xproj, const float* __restrict__ dtw){
    __shared__ float sX[16][68];
    __shared__ float sW[44][68];
    __shared__ float sC[16][48];
    __shared__ float sDT[Rr][DI];
    int ltile = blockIdx.x, k = blockIdx.y, b = blockIdx.z;
    int l0 = ltile * 16;
    int t  = threadIdx.x;
    size_t bkL = (size_t)(b*Kk + k) * Ll;

    // preload dt_projs_weight[k] transposed: sDT[r][d]
    for (int i = t; i < DI*Rr; i += 128){
        int dd = i / Rr, rr = i - dd * Rr;
        sDT[rr][dd] = dtw[((size_t)k*DI + dd) * Rr + rr];
    }

    int lme = t >> 3;          // 0..15
    int og  = t & 7;           // 0..7
    float acc[6] = {0,0,0,0,0,0};

    for (int e0 = 0; e0 < DI; e0 += 64){
        // load xs tile (16 l x 64 e), gathered per scan direction
        {
            int rr = t >> 3; int cc = (t & 7) << 3;
            const float* src = g_xc + ((size_t)b*Ll + loc_of(k, l0 + rr)) * DI + e0 + cc;
            *(float4*)&sX[rr][cc]   = *(const float4*)src;
            *(float4*)&sX[rr][cc+4] = *(const float4*)(src + 4);
        }
        // load W tile (44 x 64)
        for (int i = t; i < 44*16; i += 128){
            int rr = i >> 4; int cc = (i & 15) << 2;
            *(float4*)&sW[rr][cc] = *(const float4*)(xproj + ((size_t)(k*44 + rr)) * DI + e0 + cc);
        }
        __syncthreads();
        #pragma unroll 4
        for (int e = 0; e < 64; e++){
            float xv = sX[lme][e];
            #pragma unroll
            for (int j = 0; j < 6; j++){
                int o = og + 8*j;
                if (o < 44) acc[j] = fmaf(xv, sW[o][e], acc[j]);
            }
        }
        __syncthreads();
    }
    // stage c into smem + write B/C (and dt_r) to global
    #pragma unroll
    for (int j = 0; j < 6; j++){
        int o = og + 8*j;
        if (o < 44){
            sC[lme][o] = acc[j];
            g_c44[(bkL + l0 + lme) * 44 + o] = acc[j];
        }
    }
    __syncthreads();
    // dt projection: dts[l][d] = sum_r sDT[r][d] * sC[l][r]
    for (int i = t; i < 16*DI; i += 128){
        int l = i / DI, dd = i - l * DI;
        float a = 0.f;
        #pragma unroll
        for (int r2 = 0; r2 < Rr; r2++) a = fmaf(sDT[r2][dd], sC[l][r2], a);
        g_dts[(bkL + l0 + l) * DI + dd] = a;
    }
}

// ---------------- selective scan, chunked ----------------
// pass A: per (b,k,chunk): local scan from h=0; record h_end and prod(dA)
__global__ void k_scanA(const float* __restrict__ A_logs, const float* __restrict__ dtb){
    int blk = blockIdx.x;
    int chunk = blk & (NCHUNK - 1);
    int bk = blk >> 5;
    int k = bk & 3, b = bk >> 2;
    int d = threadIdx.x;

    float A2[Ns];
    const float* Ar = A_logs + (size_t)(k*DI + d) * Ns;
    #pragma unroll
    for (int n = 0; n < Ns; n++) A2[n] = -expf(Ar[n]) * LOG2E;
    float bias = dtb[k*DI + d];

    float h[Ns], ap[Ns];
    #pragma unroll
    for (int n = 0; n < Ns; n++){ h[n] = 0.f; ap[n] = 1.f; }

    int l0 = chunk * CLEN;
    size_t bkL = (size_t)bk * Ll;
    const float* dtp = g_dts + (bkL + l0) * DI + d;
    const float* cp  = g_c44 + (bkL + l0) * 44;
    const float* xcb = g_xc + (size_t)b * Ll * DI + d;

    for (int s = 0; s < CLEN; s++){
        int l = l0 + s;
        float delta = softplusf(dtp[0] + bias);
        float u = __ldg(xcb + (size_t)loc_of(k, l) * DI);
        float du = delta * u;
        float Bv[Ns];
        *(float4*)&Bv[0]  = __ldg((const float4*)(cp + 12));
        *(float4*)&Bv[4]  = __ldg((const float4*)(cp + 16));
        *(float4*)&Bv[8]  = __ldg((const float4*)(cp + 20));
        *(float4*)&Bv[12] = __ldg((const float4*)(cp + 24));
        #pragma unroll
        for (int n = 0; n < Ns; n++){
            float dA = ex2f(delta * A2[n]);
            h[n] = fmaf(dA, h[n], du * Bv[n]);
            ap[n] *= dA;
        }
        dtp += DI; cp += 44;
    }
    size_t o = (((size_t)bk * NCHUNK + chunk) * DI + d) * Ns;
    float4* he = (float4*)(g_hend + o);
    float4* av = (float4*)(g_aprod + o);
    #pragma unroll
    for (int q = 0; q < 4; q++){
        he[q] = make_float4(h[4*q], h[4*q+1], h[4*q+2], h[4*q+3]);
        av[q] = make_float4(ap[4*q], ap[4*q+1], ap[4*q+2], ap[4*q+3]);
    }
}

// pass B: sequential scan over 32 chunks per (b,k,d,n) -> h_init per chunk
__global__ void k_scanB(){
    int gid = blockIdx.x * blockDim.x + threadIdx.x;   // < Bb*Kk*DI*Ns = 49152
    int dn = gid % (DI*Ns);
    int bk = gid / (DI*Ns);
    size_t base = (size_t)bk * NCHUNK * DI * Ns + dn;
    float hr = 0.f;
    #pragma unroll 4
    for (int c = 0; c < NCHUNK; c++){
        size_t idx = base + (size_t)c * DI * Ns;
        g_hinit[idx] = hr;
        hr = g_aprod[idx] * hr + g_hend[idx];
    }
}

// pass C: replay with correct h_init, emit y = h.C + D*u
__global__ void k_scanC(const float* __restrict__ A_logs, const float* __restrict__ dtb,
                        const float* __restrict__ Ds){
    int blk = blockIdx.x;
    int chunk = blk & (NCHUNK - 1);
    int bk = blk >> 5;
    int k = bk & 3, b = bk >> 2;
    int d = threadIdx.x;

    float A2[Ns];
    const float* Ar = A_logs + (size_t)(k*DI + d) * Ns;
    #pragma unroll
    for (int n = 0; n < Ns; n++) A2[n] = -expf(Ar[n]) * LOG2E;
    float bias = dtb[k*DI + d];
    float Dv = Ds[k*DI + d];

    float h[Ns];
    {
        size_t o = (((size_t)bk * NCHUNK + chunk) * DI + d) * Ns;
        const float4* hi = (const float4*)(g_hinit + o);
        #pragma unroll
        for (int q = 0; q < 4; q++){
            float4 v = hi[q];
            h[4*q] = v.x; h[4*q+1] = v.y; h[4*q+2] = v.z; h[4*q+3] = v.w;
        }
    }

    int l0 = chunk * CLEN;
    size_t bkL = (size_t)bk * Ll;
    const float* dtp = g_dts + (bkL + l0) * DI + d;
    const float* cp  = g_c44 + (bkL + l0) * 44;
    const float* xcb = g_xc + (size_t)b * Ll * DI + d;
    float* yp = g_y + (bkL + l0) * DI + d;

    for (int s = 0; s < CLEN; s++){
        int l = l0 + s;
        float delta = softplusf(dtp[0] + bias);
        float u = __ldg(xcb + (size_t)loc_of(k, l) * DI);
        float du = delta * u;
        float Bv[Ns], Cv[Ns];
        *(float4*)&Bv[0]  = __ldg((const float4*)(cp + 12));
        *(float4*)&Bv[4]  = __ldg((const float4*)(cp + 16));
        *(float4*)&Bv[8]  = __ldg((const float4*)(cp + 20));
        *(float4*)&Bv[12] = __ldg((const float4*)(cp + 24));
        *(float4*)&Cv[0]  = __ldg((const float4*)(cp + 28));
        *(float4*)&Cv[4]  = __ldg((const float4*)(cp + 32));
        *(float4*)&Cv[8]  = __ldg((const float4*)(cp + 36));
        *(float4*)&Cv[12] = __ldg((const float4*)(cp + 40));
        float acc = 0.f;
        #pragma unroll
        for (int n = 0; n < Ns; n++){
            float dA = ex2f(delta * A2[n]);
            h[n] = fmaf(dA, h[n], du * Bv[n]);
            acc = fmaf(h[n], Cv[n], acc);
        }
        yp[0] = fmaf(Dv, u, acc);
        dtp += DI; cp += 44; yp += DI;
    }
}

// ---------------- merge 4 directions + LayerNorm + gate ----------------
__global__ void k_ln(const float* __restrict__ gam, const float* __restrict__ bet){
    int p = blockIdx.x % Ll;
    int b = blockIdx.x / Ll;
    int h = p / Ww, w = p % Ww;
    int l1 = w * Ww + h;
    int l2 = Ll - 1 - p;
    int l3 = Ll - 1 - l1;
    size_t bbase = (size_t)b * Kk * Ll;
    int t = threadIdx.x;
    float v[3];
    float s1 = 0.f, s2 = 0.f;
    #pragma unroll
    for (int j = 0; j < 3; j++){
        int d = t + j * 128;
        float y = g_y[(bbase + 0*Ll + p ) * DI + d]
                + g_y[(bbase + 1*Ll + l1) * DI + d]
                + g_y[(bbase + 2*Ll + l2) * DI + d]
                + g_y[(bbase + 3*Ll + l3) * DI + d];
        v[j] = y; s1 += y; s2 += y*y;
    }
    // block reduction (4 warps)
    #pragma unroll
    for (int off = 16; off > 0; off >>= 1){
        s1 += __shfl_xor_sync(0xffffffffu, s1, off);
        s2 += __shfl_xor_sync(0xffffffffu, s2, off);
    }
    __shared__ float r1[4], r2[4];
    int warp = t >> 5, lane = t & 31;
    if (lane == 0){ r1[warp] = s1; r2[warp] = s2; }
    __syncthreads();
    float S1 = r1[0] + r1[1] + r1[2] + r1[3];
    float S2 = r2[0] + r2[1] + r2[2] + r2[3];
    float mu = S1 * (1.f / DI);
    float var = S2 * (1.f / DI) - mu * mu;
    float rstd = rsqrtf(var + 1e-5f);
    const float* zrow = g_xz + ((size_t)b*Ll + p) * (2*DI) + DI;
    float* grow = g_g + ((size_t)b*Ll + p) * DI;
    #pragma unroll
    for (int j = 0; j < 3; j++){
        int d = t + j * 128;
        float zn = zrow[d];
        float gate = zn * sigmoidf(zn);
        grow[d] = ((v[j] - mu) * rstd * gam[d] + bet[d]) * gate;
    }
}

// ---------------- launch ----------------
extern "C" void kernel_launch(void* const* d_in, const int* in_sizes, int n_in,
                              void* d_out, int out_size){
    const float* x      = (const float*)d_in[0];
    const float* in_w   = (const float*)d_in[1];
    const float* conv_w = (const float*)d_in[2];
    const float* conv_b = (const float*)d_in[3];
    const float* xproj  = (const float*)d_in[4];
    const float* dtw    = (const float*)d_in[5];
    const float* dtb    = (const float*)d_in[6];
    const float* Alog   = (const float*)d_in[7];
    const float* Ds     = (const float*)d_in[8];
    const float* gam    = (const float*)d_in[9];
    const float* bet    = (const float*)d_in[10];
    const float* outw   = (const float*)d_in[11];
    float* out = (float*)d_out;

    k_inproj <<<dim3((2*DI)/64, (Bb*Ll)/64), 256>>>(x, in_w);
    k_conv   <<<Bb*Ll, 128>>>(conv_w, conv_b);
    k_xdbl   <<<dim3(Ll/16, Kk, Bb), 128>>>(xproj, dtw);
    k_scanA  <<<Bb*Kk*NCHUNK, DI>>>(Alog, dtb);
    k_scanB  <<<(Bb*Kk*DI*Ns)/256, 256>>>();
    k_scanC  <<<Bb*Kk*NCHUNK, DI>>>(Alog, dtb, Ds);
    k_ln     <<<Bb*Ll, 128>>>(gam, bet);
    k_outproj<<<dim3(DMo/64, (Bb*Ll)/64), 256>>>(outw, out);
}

// round 2
// speedup vs baseline: 1.1665x; 1.1665x over previous
#include <cuda_runtime.h>
#include <cstdint>

#define Bb 2
#define Hh 48
#define Ww 48
#define DMo 192
#define Ns 16
#define DI 384
#define Rr 12
#define Kk 4
#define Ll (Hh*Ww)          // 2304
#define NCHUNK 32
#define CLEN (Ll/NCHUNK)    // 72
#define LOG2E 1.4426950408889634f
#define LN2 0.6931471805599453f

// ---------------- static device scratch ----------------
__device__ float g_xz  [(size_t)Bb*Ll*(2*DI)];      // in_proj output (b,l,768)
__device__ float g_xc  [(size_t)Bb*Ll*DI];          // conv+silu output (b,l,d)
__device__ float g_c44 [(size_t)Bb*Kk*Ll*44];       // (b,k,l,44) [0:12 dt_r | 12:28 B | 28:44 C]
__device__ float g_dts [(size_t)Bb*Kk*Ll*DI];       // DELTA (post bias+softplus) (b,k,l,d)
__device__ float g_y   [(size_t)Bb*Kk*Ll*DI];       // per-direction scan output (b,k,l,d)
__device__ float g_g   [(size_t)Bb*Ll*DI];          // post-LN, gated (b,l,d)
__device__ float g_hend [(size_t)Bb*Kk*NCHUNK*DI*Ns];
__device__ float g_aprod[(size_t)Bb*Kk*NCHUNK*DI*Ns];
__device__ float g_hinit[(size_t)Bb*Kk*NCHUNK*DI*Ns];

// ---------------- helpers ----------------
__device__ __forceinline__ float ex2f(float x){ float y; asm("ex2.approx.f32 %0, %1;" : "=f"(y) : "f"(x)); return y; }
__device__ __forceinline__ float lg2f(float x){ float y; asm("lg2.approx.f32 %0, %1;" : "=f"(y) : "f"(x)); return y; }

__device__ __forceinline__ float softplus_fast(float x){
    if (x > 20.f) return x;
    float e = ex2f(x * LOG2E);
    return LN2 * lg2f(1.f + e);
}
__device__ __forceinline__ float sigmoidf(float x){
    return 1.f / (1.f + __expf(-x));
}

// p[n] = r^(n+1), log-depth
__device__ __forceinline__ void powers16(float r, float* p){
    p[0]=r;        p[1]=r*r;      p[2]=p[1]*r;    p[3]=p[1]*p[1];
    p[4]=p[3]*r;   p[5]=p[3]*p[1];p[6]=p[3]*p[2]; p[7]=p[3]*p[3];
    p[8]=p[7]*r;   p[9]=p[7]*p[1];p[10]=p[7]*p[2];p[11]=p[7]*p[3];
    p[12]=p[7]*p[4];p[13]=p[7]*p[5];p[14]=p[7]*p[6];p[15]=p[7]*p[7];
}

// scan-step l of direction k reads raster location loc_of(k,l)
__device__ __forceinline__ int loc_of(int k, int l){
    int l2 = (k >= 2) ? (Ll - 1 - l) : l;
    if (k & 1){ int w = l2 / Ww; int h = l2 - w * Ww; return h * Ww + w; }
    return l2;
}

// ---------------- generic NT GEMM: C[M,N] = A[M,K] * B[N,K]^T ----------------
__device__ __forceinline__ void gemm_nt(const float* __restrict__ A, const float* __restrict__ B,
                                        float* __restrict__ C, int M, int N, int K){
    __shared__ float As[16][68];
    __shared__ float Bs[16][68];
    int t  = threadIdx.x;
    int tx = t & 15, ty = t >> 4;
    int m0 = blockIdx.y * 64, n0 = blockIdx.x * 64;
    float acc[4][4] = {};
    int r  = t >> 2;
    int kc = (t & 3) << 2;
    const float* Ap = A + (size_t)(m0 + r) * K + kc;
    const float* Bp = B + (size_t)(n0 + r) * K + kc;
    for (int k0 = 0; k0 < K; k0 += 16){
        float4 av = *(const float4*)(Ap + k0);
        float4 bv = *(const float4*)(Bp + k0);
        As[kc+0][r] = av.x; As[kc+1][r] = av.y; As[kc+2][r] = av.z; As[kc+3][r] = av.w;
        Bs[kc+0][r] = bv.x; Bs[kc+1][r] = bv.y; Bs[kc+2][r] = bv.z; Bs[kc+3][r] = bv.w;
        __syncthreads();
        #pragma unroll
        for (int kk = 0; kk < 16; kk++){
            float4 a = *(const float4*)&As[kk][ty << 2];
            float4 b = *(const float4*)&Bs[kk][tx << 2];
            acc[0][0] = fmaf(a.x, b.x, acc[0][0]); acc[0][1] = fmaf(a.x, b.y, acc[0][1]);
            acc[0][2] = fmaf(a.x, b.z, acc[0][2]); acc[0][3] = fmaf(a.x, b.w, acc[0][3]);
            acc[1][0] = fmaf(a.y, b.x, acc[1][0]); acc[1][1] = fmaf(a.y, b.y, acc[1][1]);
            acc[1][2] = fmaf(a.y, b.z, acc[1][2]); acc[1][3] = fmaf(a.y, b.w, acc[1][3]);
            acc[2][0] = fmaf(a.z, b.x, acc[2][0]); acc[2][1] = fmaf(a.z, b.y, acc[2][1]);
            acc[2][2] = fmaf(a.z, b.z, acc[2][2]); acc[2][3] = fmaf(a.z, b.w, acc[2][3]);
            acc[3][0] = fmaf(a.w, b.x, acc[3][0]); acc[3][1] = fmaf(a.w, b.y, acc[3][1]);
            acc[3][2] = fmaf(a.w, b.z, acc[3][2]); acc[3][3] = fmaf(a.w, b.w, acc[3][3]);
        }
        __syncthreads();
    }
    #pragma unroll
    for (int i = 0; i < 4; i++){
        float4 v = make_float4(acc[i][0], acc[i][1], acc[i][2], acc[i][3]);
        *(float4*)&C[(size_t)(m0 + ty*4 + i) * N + n0 + tx*4] = v;
    }
}

__global__ void k_inproj(const float* __restrict__ x, const float* __restrict__ w){
    gemm_nt(x, w, g_xz, Bb*Ll, 2*DI, DMo);
}
__global__ void k_outproj(const float* __restrict__ w, float* __restrict__ out){
    gemm_nt(g_g, w, out, Bb*Ll, DMo, DI);
}

// ---------------- depthwise conv 3x3 + bias + SiLU (channel-last) ----------------
__global__ void k_conv(const float* __restrict__ cw, const float* __restrict__ cb){
    int p = blockIdx.x % Ll;
    int b = blockIdx.x / Ll;
    int h = p / Ww, w = p % Ww;
    const float* base = g_xz + (size_t)b * Ll * (2*DI);
    #pragma unroll
    for (int j = 0; j < 3; j++){
        int d = threadIdx.x + j * 128;
        float acc = cb[d];
        const float* wr = cw + d * 9;
        #pragma unroll
        for (int dh = -1; dh <= 1; dh++){
            int hh = h + dh;
            if ((unsigned)hh >= (unsigned)Hh) continue;
            #pragma unroll
            for (int dw = -1; dw <= 1; dw++){
                int ww2 = w + dw;
                if ((unsigned)ww2 >= (unsigned)Ww) continue;
                acc = fmaf(base[(size_t)(hh*Ww + ww2) * (2*DI) + d], wr[(dh+1)*3 + (dw+1)], acc);
            }
        }
        g_xc[((size_t)b*Ll + p) * DI + d] = acc * sigmoidf(acc);
    }
}

// ---------------- x_proj + dt_proj + bias + softplus ----------------
__global__ void k_xdbl(const float* __restrict__ xproj, const float* __restrict__ dtw,
                       const float* __restrict__ dtb){
    __shared__ float sX[16][68];
    __shared__ float sW[44][68];
    __shared__ float sC[16][48];
    __shared__ float sDT[Rr][DI];
    __shared__ float sBias[DI];
    int ltile = blockIdx.x, k = blockIdx.y, b = blockIdx.z;
    int l0 = ltile * 16;
    int t  = threadIdx.x;
    size_t bkL = (size_t)(b*Kk + k) * Ll;

    for (int i = t; i < DI*Rr; i += 128){
        int dd = i / Rr, rr = i - dd * Rr;
        sDT[rr][dd] = dtw[((size_t)k*DI + dd) * Rr + rr];
    }
    for (int i = t; i < DI; i += 128) sBias[i] = dtb[k*DI + i];

    int lme = t >> 3;
    int og  = t & 7;
    float acc[6] = {0,0,0,0,0,0};

    for (int e0 = 0; e0 < DI; e0 += 64){
        {
            int rr = t >> 3; int cc = (t & 7) << 3;
            const float* src = g_xc + ((size_t)b*Ll + loc_of(k, l0 + rr)) * DI + e0 + cc;
            *(float4*)&sX[rr][cc]   = *(const float4*)src;
            *(float4*)&sX[rr][cc+4] = *(const float4*)(src + 4);
        }
        for (int i = t; i < 44*16; i += 128){
            int rr = i >> 4; int cc = (i & 15) << 2;
            *(float4*)&sW[rr][cc] = *(const float4*)(xproj + ((size_t)(k*44 + rr)) * DI + e0 + cc);
        }
        __syncthreads();
        #pragma unroll 4
        for (int e = 0; e < 64; e++){
            float xv = sX[lme][e];
            #pragma unroll
            for (int j = 0; j < 6; j++){
                int o = og + 8*j;
                if (o < 44) acc[j] = fmaf(xv, sW[o][e], acc[j]);
            }
        }
        __syncthreads();
    }
    #pragma unroll
    for (int j = 0; j < 6; j++){
        int o = og + 8*j;
        if (o < 44){
            sC[lme][o] = acc[j];
            g_c44[(bkL + l0 + lme) * 44 + o] = acc[j];
        }
    }
    __syncthreads();
    // dt projection + bias + softplus (delta stored directly)
    for (int i = t; i < 16*DI; i += 128){
        int l = i / DI, dd = i - l * DI;
        float a = sBias[dd];
        #pragma unroll
        for (int r2 = 0; r2 < Rr; r2++) a = fmaf(sDT[r2][dd], sC[l][r2], a);
        g_dts[(bkL + l0 + l) * DI + dd] = softplus_fast(a);
    }
}

// ---------------- selective scan, chunked ----------------
// pass A: local scan from h=0; record h_end and prod(dA)
__global__ void __launch_bounds__(DI, 2) k_scanA(const float* __restrict__ A_logs){
    int blk = blockIdx.x;
    int chunk = blk & (NCHUNK - 1);
    int bk = blk >> 5;
    int k = bk & 3, b = bk >> 2;
    int d = threadIdx.x;

    float A2[Ns];
    const float* Ar = A_logs + (size_t)(k*DI + d) * Ns;
    #pragma unroll
    for (int n = 0; n < Ns; n++) A2[n] = -expf(Ar[n]) * LOG2E;
    bool geo = (A2[0] != 0.f);
    #pragma unroll
    for (int n = 1; n < Ns; n++)
        geo = geo && (fabsf(A2[n] - (float)(n+1)*A2[0]) <= 1e-4f * fabsf(A2[n]));

    float h[Ns];
    #pragma unroll
    for (int n = 0; n < Ns; n++) h[n] = 0.f;

    int l0 = chunk * CLEN;
    size_t bkL = (size_t)bk * Ll;
    const float* dtp = g_dts + (bkL + l0) * DI + d;
    const float* cp  = g_c44 + (bkL + l0) * 44;
    const float* xcb = g_xc + (size_t)b * Ll * DI + d;
    float ap[Ns];

    if (geo){
        float A1 = A2[0];
        float rp = 1.f;
        for (int s = 0; s < CLEN; s++){
            int l = l0 + s;
            float delta = dtp[0];
            float u = __ldg(xcb + (size_t)loc_of(k, l) * DI);
            float du = delta * u;
            float r = ex2f(delta * A1);
            float p[Ns]; powers16(r, p);
            #pragma unroll
            for (int q = 0; q < 4; q++){
                float4 bq = __ldg((const float4*)(cp + 12 + 4*q));
                h[4*q+0] = fmaf(p[4*q+0], h[4*q+0], du * bq.x);
                h[4*q+1] = fmaf(p[4*q+1], h[4*q+1], du * bq.y);
                h[4*q+2] = fmaf(p[4*q+2], h[4*q+2], du * bq.z);
                h[4*q+3] = fmaf(p[4*q+3], h[4*q+3], du * bq.w);
            }
            rp *= r;
            dtp += DI; cp += 44;
        }
        powers16(rp, ap);
    } else {
        #pragma unroll
        for (int n = 0; n < Ns; n++) ap[n] = 1.f;
        for (int s = 0; s < CLEN; s++){
            int l = l0 + s;
            float delta = dtp[0];
            float u = __ldg(xcb + (size_t)loc_of(k, l) * DI);
            float du = delta * u;
            float Bv[Ns];
            *(float4*)&Bv[0]  = __ldg((const float4*)(cp + 12));
            *(float4*)&Bv[4]  = __ldg((const float4*)(cp + 16));
            *(float4*)&Bv[8]  = __ldg((const float4*)(cp + 20));
            *(float4*)&Bv[12] = __ldg((const float4*)(cp + 24));
            #pragma unroll
            for (int n = 0; n < Ns; n++){
                float dA = ex2f(delta * A2[n]);
                h[n] = fmaf(dA, h[n], du * Bv[n]);
                ap[n] *= dA;
            }
            dtp += DI; cp += 44;
        }
    }
    size_t o = (((size_t)bk * NCHUNK + chunk) * DI + d) * Ns;
    float4* he = (float4*)(g_hend + o);
    float4* av = (float4*)(g_aprod + o);
    #pragma unroll
    for (int q = 0; q < 4; q++){
        he[q] = make_float4(h[4*q], h[4*q+1], h[4*q+2], h[4*q+3]);
        av[q] = make_float4(ap[4*q], ap[4*q+1], ap[4*q+2], ap[4*q+3]);
    }
}

// pass B: sequential scan over chunks -> h_init per chunk
__global__ void k_scanB(){
    int gid = blockIdx.x * blockDim.x + threadIdx.x;
    int dn = gid % (DI*Ns);
    int bk = gid / (DI*Ns);
    size_t base = (size_t)bk * NCHUNK * DI * Ns + dn;
    float hr = 0.f;
    #pragma unroll 4
    for (int c = 0; c < NCHUNK; c++){
        size_t idx = base + (size_t)c * DI * Ns;
        g_hinit[idx] = hr;
        hr = g_aprod[idx] * hr + g_hend[idx];
    }
}

// pass C: replay with correct h_init, emit y = h.C + D*u
__global__ void __launch_bounds__(DI, 2) k_scanC(const float* __restrict__ A_logs,
                                                 const float* __restrict__ Ds){
    int blk = blockIdx.x;
    int chunk = blk & (NCHUNK - 1);
    int bk = blk >> 5;
    int k = bk & 3, b = bk >> 2;
    int d = threadIdx.x;

    float A2[Ns];
    const float* Ar = A_logs + (size_t)(k*DI + d) * Ns;
    #pragma unroll
    for (int n = 0; n < Ns; n++) A2[n] = -expf(Ar[n]) * LOG2E;
    bool geo = (A2[0] != 0.f);
    #pragma unroll
    for (int n = 1; n < Ns; n++)
        geo = geo && (fabsf(A2[n] - (float)(n+1)*A2[0]) <= 1e-4f * fabsf(A2[n]));
    float Dv = Ds[k*DI + d];

    float h[Ns];
    {
        size_t o = (((size_t)bk * NCHUNK + chunk) * DI + d) * Ns;
        const float4* hi = (const float4*)(g_hinit + o);
        #pragma unroll
        for (int q = 0; q < 4; q++){
            float4 v = hi[q];
            h[4*q] = v.x; h[4*q+1] = v.y; h[4*q+2] = v.z; h[4*q+3] = v.w;
        }
    }

    int l0 = chunk * CLEN;
    size_t bkL = (size_t)bk * Ll;
    const float* dtp = g_dts + (bkL + l0) * DI + d;
    const float* cp  = g_c44 + (bkL + l0) * 44;
    const float* xcb = g_xc + (size_t)b * Ll * DI + d;
    float* yp = g_y + (bkL + l0) * DI + d;

    if (geo){
        float A1 = A2[0];
        for (int s = 0; s < CLEN; s++){
            int l = l0 + s;
            float delta = dtp[0];
            float u = __ldg(xcb + (size_t)loc_of(k, l) * DI);
            float du = delta * u;
            float r = ex2f(delta * A1);
            float p[Ns]; powers16(r, p);
            float acc = 0.f;
            #pragma unroll
            for (int q = 0; q < 4; q++){
                float4 bq = __ldg((const float4*)(cp + 12 + 4*q));
                float4 cq = __ldg((const float4*)(cp + 28 + 4*q));
                h[4*q+0] = fmaf(p[4*q+0], h[4*q+0], du * bq.x); acc = fmaf(h[4*q+0], cq.x, acc);
                h[4*q+1] = fmaf(p[4*q+1], h[4*q+1], du * bq.y); acc = fmaf(h[4*q+1], cq.y, acc);
                h[4*q+2] = fmaf(p[4*q+2], h[4*q+2], du * bq.z); acc = fmaf(h[4*q+2], cq.z, acc);
                h[4*q+3] = fmaf(p[4*q+3], h[4*q+3], du * bq.w); acc = fmaf(h[4*q+3], cq.w, acc);
            }
            yp[0] = fmaf(Dv, u, acc);
            dtp += DI; cp += 44; yp += DI;
        }
    } else {
        for (int s = 0; s < CLEN; s++){
            int l = l0 + s;
            float delta = dtp[0];
            float u = __ldg(xcb + (size_t)loc_of(k, l) * DI);
            float du = delta * u;
            float acc = 0.f;
            #pragma unroll
            for (int q = 0; q < 4; q++){
                float4 bq = __ldg((const float4*)(cp + 12 + 4*q));
                float4 cq = __ldg((const float4*)(cp + 28 + 4*q));
                float dA0 = ex2f(delta * A2[4*q+0]);
                float dA1 = ex2f(delta * A2[4*q+1]);
                float dA2 = ex2f(delta * A2[4*q+2]);
                float dA3 = ex2f(delta * A2[4*q+3]);
                h[4*q+0] = fmaf(dA0, h[4*q+0], du * bq.x); acc = fmaf(h[4*q+0], cq.x, acc);
                h[4*q+1] = fmaf(dA1, h[4*q+1], du * bq.y); acc = fmaf(h[4*q+1], cq.y, acc);
                h[4*q+2] = fmaf(dA2, h[4*q+2], du * bq.z); acc = fmaf(h[4*q+2], cq.z, acc);
                h[4*q+3] = fmaf(dA3, h[4*q+3], du * bq.w); acc = fmaf(h[4*q+3], cq.w, acc);
            }
            yp[0] = fmaf(Dv, u, acc);
            dtp += DI; cp += 44; yp += DI;
        }
    }
}

// ---------------- merge 4 directions + LayerNorm + gate ----------------
__global__ void k_ln(const float* __restrict__ gam, const float* __restrict__ bet){
    int p = blockIdx.x % Ll;
    int b = blockIdx.x / Ll;
    int h = p / Ww, w = p % Ww;
    int l1 = w * Ww + h;
    int l2 = Ll - 1 - p;
    int l3 = Ll - 1 - l1;
    size_t bbase = (size_t)b * Kk * Ll;
    int t = threadIdx.x;
    float v[3];
    float s1 = 0.f, s2 = 0.f;
    #pragma unroll
    for (int j = 0; j < 3; j++){
        int d = t + j * 128;
        float y = g_y[(bbase + 0*Ll + p ) * DI + d]
                + g_y[(bbase + 1*Ll + l1) * DI + d]
                + g_y[(bbase + 2*Ll + l2) * DI + d]
                + g_y[(bbase + 3*Ll + l3) * DI + d];
        v[j] = y; s1 += y; s2 += y*y;
    }
    #pragma unroll
    for (int off = 16; off > 0; off >>= 1){
        s1 += __shfl_xor_sync(0xffffffffu, s1, off);
        s2 += __shfl_xor_sync(0xffffffffu, s2, off);
    }
    __shared__ float r1[4], r2[4];
    int warp = t >> 5, lane = t & 31;
    if (lane == 0){ r1[warp] = s1; r2[warp] = s2; }
    __syncthreads();
    float S1 = r1[0] + r1[1] + r1[2] + r1[3];
    float S2 = r2[0] + r2[1] + r2[2] + r2[3];
    float mu = S1 * (1.f / DI);
    float var = S2 * (1.f / DI) - mu * mu;
    float rstd = rsqrtf(var + 1e-5f);
    const float* zrow = g_xz + ((size_t)b*Ll + p) * (2*DI) + DI;
    float* grow = g_g + ((size_t)b*Ll + p) * DI;
    #pragma unroll
    for (int j = 0; j < 3; j++){
        int d = t + j * 128;
        float zn = zrow[d];
        float gate = zn * sigmoidf(zn);
        grow[d] = ((v[j] - mu) * rstd * gam[d] + bet[d]) * gate;
    }
}

// ---------------- launch ----------------
extern "C" void kernel_launch(void* const* d_in, const int* in_sizes, int n_in,
                              void* d_out, int out_size){
    const float* x      = (const float*)d_in[0];
    const float* in_w   = (const float*)d_in[1];
    const float* conv_w = (const float*)d_in[2];
    const float* conv_b = (const float*)d_in[3];
    const float* xproj  = (const float*)d_in[4];
    const float* dtw    = (const float*)d_in[5];
    const float* dtb    = (const float*)d_in[6];
    const float* Alog   = (const float*)d_in[7];
    const float* Ds     = (const float*)d_in[8];
    const float* gam    = (const float*)d_in[9];
    const float* bet    = (const float*)d_in[10];
    const float* outw   = (const float*)d_in[11];
    float* out = (float*)d_out;

    k_inproj <<<dim3((2*DI)/64, (Bb*Ll)/64), 256>>>(x, in_w);
    k_conv   <<<Bb*Ll, 128>>>(conv_w, conv_b);
    k_xdbl   <<<dim3(Ll/16, Kk, Bb), 128>>>(xproj, dtw, dtb);
    k_scanA  <<<Bb*Kk*NCHUNK, DI>>>(Alog);
    k_scanB  <<<(Bb*Kk*DI*Ns)/256, 256>>>();
    k_scanC  <<<Bb*Kk*NCHUNK, DI>>>(Alog, Ds);
    k_ln     <<<Bb*Ll, 128>>>(gam, bet);
    k_outproj<<<dim3(DMo/64, (Bb*Ll)/64), 256>>>(outw, out);
}

// round 3
// speedup vs baseline: 1.4836x; 1.2719x over previous
#include <cuda_runtime.h>
#include <cstdint>

typedef unsigned long long ull;

#define Bb 2
#define Hh 48
#define Ww 48
#define DMo 192
#define Ns 16
#define DI 384
#define Rr 12
#define Kk 4
#define Ll (Hh*Ww)          // 2304
#define NCHUNK 32
#define CLEN (Ll/NCHUNK)    // 72
#define LOG2E 1.4426950408889634f
#define LN2 0.6931471805599453f

// ---------------- static device scratch ----------------
__device__ float g_xz  [(size_t)Bb*Ll*(2*DI)];      // in_proj output (b,l,768)
__device__ float g_xc  [(size_t)Bb*Ll*DI];          // conv+silu output (b,l,d)
__device__ float g_c176[(size_t)Bb*Ll*176];         // (b,p,176): per k: [k*44: 12 dt_r | +12: B(16) | +28: C(16)]
__device__ float g_dts [(size_t)Bb*Kk*Ll*DI];       // DELTA (post bias+softplus) (b,k,l,d)
__device__ float g_y   [(size_t)Bb*Kk*Ll*DI];       // per-direction scan output (b,k,l,d)
__device__ float g_g   [(size_t)Bb*Ll*DI];          // post-LN, gated (b,l,d)
__device__ float g_hend [(size_t)Bb*Kk*NCHUNK*DI*Ns];
__device__ float g_aprod[(size_t)Bb*Kk*NCHUNK*DI*Ns];
__device__ float g_hinit[(size_t)Bb*Kk*NCHUNK*DI*Ns];

// ---------------- helpers ----------------
__device__ __forceinline__ float ex2f(float x){ float y; asm("ex2.approx.f32 %0, %1;" : "=f"(y) : "f"(x)); return y; }
__device__ __forceinline__ float lg2f(float x){ float y; asm("lg2.approx.f32 %0, %1;" : "=f"(y) : "f"(x)); return y; }

__device__ __forceinline__ float softplus_fast(float x){
    if (x > 20.f) return x;
    float e = ex2f(x * LOG2E);
    return LN2 * lg2f(1.f + e);
}
__device__ __forceinline__ float sigmoidf(float x){
    return 1.f / (1.f + __expf(-x));
}

// packed fp32x2 ops (sm_103a; FFMA2 only reachable via PTX)
__device__ __forceinline__ ull pk2(float lo, float hi){
    ull r; asm("mov.b64 %0, {%1, %2};" : "=l"(r) : "r"(__float_as_uint(lo)), "r"(__float_as_uint(hi)));
    return r;
}
__device__ __forceinline__ void upk2(ull v, float& lo, float& hi){
    unsigned a, b; asm("mov.b64 {%0, %1}, %2;" : "=r"(a), "=r"(b) : "l"(v));
    lo = __uint_as_float(a); hi = __uint_as_float(b);
}
__device__ __forceinline__ ull fma2(ull a, ull b, ull c){
    ull d; asm("fma.rn.f32x2 %0, %1, %2, %3;" : "=l"(d) : "l"(a), "l"(b), "l"(c));
    return d;
}
__device__ __forceinline__ ull mul2(ull a, ull b){
    ull d; asm("mul.rn.f32x2 %0, %1, %2;" : "=l"(d) : "l"(a), "l"(b));
    return d;
}

// pair powers: p[i] = (r^(2i+1), r^(2i+2)), i=0..7
__device__ __forceinline__ void powers16p(float r, ull* p){
    float r2 = r*r;
    ull rr2 = pk2(r2, r2);
    p[0] = pk2(r, r2);
    p[1] = mul2(p[0], rr2);
    p[2] = mul2(p[1], rr2);
    p[3] = mul2(p[2], rr2);
    p[4] = mul2(p[3], rr2);
    p[5] = mul2(p[4], rr2);
    p[6] = mul2(p[5], rr2);
    p[7] = mul2(p[6], rr2);
}

// scan-step l of direction k reads raster location loc_of(k,l) (involution)
__device__ __forceinline__ int loc_of(int k, int l){
    int l2 = (k >= 2) ? (Ll - 1 - l) : l;
    if (k & 1){ int w = l2 / Ww; int h = l2 - w * Ww; return h * Ww + w; }
    return l2;
}

// ---------------- NT GEMM with FFMA2: C[M,Nrow] = A[M,K] * B[Nrow,K]^T ----------------
// BM=BN=64, BK=16, 256 threads. M mult of 64, K mult of 16, Nrow mult of 4.
// n-tiles may overhang Nrow (loads clamped, stores guarded).
__device__ __forceinline__ void gemm_nt2(const float* __restrict__ A, const float* __restrict__ B,
                                         float* __restrict__ C, int K, int Nrow){
    __shared__ float As[16][68];
    __shared__ float Bs[16][68];
    int t  = threadIdx.x;
    int tx = t & 15, ty = t >> 4;
    int m0 = blockIdx.y * 64, n0 = blockIdx.x * 64;
    ull acc[4][2] = {};
    int r  = t >> 2;
    int kc = (t & 3) << 2;
    int brow = n0 + r; if (brow >= Nrow) brow = Nrow - 1;
    const float* Ap = A + (size_t)(m0 + r) * K + kc;
    const float* Bp = B + (size_t)brow * K + kc;
    for (int k0 = 0; k0 < K; k0 += 16){
        float4 av = *(const float4*)(Ap + k0);
        float4 bv = *(const float4*)(Bp + k0);
        As[kc+0][r] = av.x; As[kc+1][r] = av.y; As[kc+2][r] = av.z; As[kc+3][r] = av.w;
        Bs[kc+0][r] = bv.x; Bs[kc+1][r] = bv.y; Bs[kc+2][r] = bv.z; Bs[kc+3][r] = bv.w;
        __syncthreads();
        #pragma unroll
        for (int kk = 0; kk < 16; kk++){
            float4 a = *(const float4*)&As[kk][ty << 2];
            const ull* bp = (const ull*)&Bs[kk][tx << 2];
            ull b0 = bp[0], b1 = bp[1];
            ull a0 = pk2(a.x, a.x), a1 = pk2(a.y, a.y), a2 = pk2(a.z, a.z), a3 = pk2(a.w, a.w);
            acc[0][0] = fma2(a0, b0, acc[0][0]); acc[0][1] = fma2(a0, b1, acc[0][1]);
            acc[1][0] = fma2(a1, b0, acc[1][0]); acc[1][1] = fma2(a1, b1, acc[1][1]);
            acc[2][0] = fma2(a2, b0, acc[2][0]); acc[2][1] = fma2(a2, b1, acc[2][1]);
            acc[3][0] = fma2(a3, b0, acc[3][0]); acc[3][1] = fma2(a3, b1, acc[3][1]);
        }
        __syncthreads();
    }
    int nc = n0 + (tx << 2);
    if (nc < Nrow){
        #pragma unroll
        for (int i = 0; i < 4; i++){
            ulonglong2 v; v.x = acc[i][0]; v.y = acc[i][1];
            *(ulonglong2*)&C[(size_t)(m0 + ty*4 + i) * Nrow + nc] = v;
        }
    }
}

__global__ void k_inproj(const float* __restrict__ x, const float* __restrict__ w){
    gemm_nt2(x, w, g_xz, DMo, 2*DI);
}
__global__ void k_outproj(const float* __restrict__ w, float* __restrict__ out){
    gemm_nt2(g_g, w, out, DI, DMo);
}
// combined x_proj for all 4 directions: xproj is contiguous (176,384)
__global__ void k_cproj(const float* __restrict__ xproj){
    gemm_nt2(g_xc, xproj, g_c176, DI, 176);
}

// ---------------- depthwise conv 3x3 + bias + SiLU (channel-last) ----------------
__global__ void k_conv(const float* __restrict__ cw, const float* __restrict__ cb){
    int p = blockIdx.x % Ll;
    int b = blockIdx.x / Ll;
    int h = p / Ww, w = p % Ww;
    const float* base = g_xz + (size_t)b * Ll * (2*DI);
    #pragma unroll
    for (int j = 0; j < 3; j++){
        int d = threadIdx.x + j * 128;
        float acc = cb[d];
        const float* wr = cw + d * 9;
        #pragma unroll
        for (int dh = -1; dh <= 1; dh++){
            int hh = h + dh;
            if ((unsigned)hh >= (unsigned)Hh) continue;
            #pragma unroll
            for (int dw = -1; dw <= 1; dw++){
                int ww2 = w + dw;
                if ((unsigned)ww2 >= (unsigned)Ww) continue;
                acc = fmaf(base[(size_t)(hh*Ww + ww2) * (2*DI) + d], wr[(dh+1)*3 + (dw+1)], acc);
            }
        }
        g_xc[((size_t)b*Ll + p) * DI + d] = acc * sigmoidf(acc);
    }
}

// ---------------- dt projection + bias + softplus ----------------
// grid (Ll/32, K, B), 384 threads. delta[b,k,l,d] = softplus(bias_d + sum_r w[d][r]*dtr[l][r])
__global__ void k_dts(const float* __restrict__ dtw, const float* __restrict__ dtb){
    __shared__ float sc[32][12];
    int ltile = blockIdx.x, k = blockIdx.y, b = blockIdx.z;
    int l0 = ltile * 32;
    int t = threadIdx.x;
    int d = t;
    size_t bkL = (size_t)(b*Kk + k) * Ll;
    const float* cbase = g_c176 + (size_t)b * Ll * 176 + k * 44;

    // load 32 rows x 12 dt_r values (gathered by scan order)
    if (t < 32*12){
        int row = t / 12, col = t - row * 12;
        sc[row][col] = cbase[(size_t)loc_of(k, l0 + row) * 176 + col];
    }
    float wreg[Rr];
    #pragma unroll
    for (int r = 0; r < Rr; r++) wreg[r] = dtw[((size_t)k*DI + d) * Rr + r];
    float bias = dtb[k*DI + d];
    __syncthreads();

    float* dp = g_dts + (bkL + l0) * DI + d;
    #pragma unroll 4
    for (int l = 0; l < 32; l++){
        float4 c0 = *(const float4*)&sc[l][0];
        float4 c1 = *(const float4*)&sc[l][4];
        float4 c2 = *(const float4*)&sc[l][8];
        float a = bias;
        a = fmaf(wreg[0], c0.x, a); a = fmaf(wreg[1], c0.y, a);
        a = fmaf(wreg[2], c0.z, a); a = fmaf(wreg[3], c0.w, a);
        a = fmaf(wreg[4], c1.x, a); a = fmaf(wreg[5], c1.y, a);
        a = fmaf(wreg[6], c1.z, a); a = fmaf(wreg[7], c1.w, a);
        a = fmaf(wreg[8], c2.x, a); a = fmaf(wreg[9], c2.y, a);
        a = fmaf(wreg[10], c2.z, a); a = fmaf(wreg[11], c2.w, a);
        dp[(size_t)l * DI] = softplus_fast(a);
    }
}

// ---------------- selective scan, chunked ----------------
// pass A: local scan from h=0; record h_end and prod(dA)
__global__ void __launch_bounds__(DI, 2) k_scanA(const float* __restrict__ A_logs){
    int blk = blockIdx.x;
    int chunk = blk & (NCHUNK - 1);
    int bk = blk >> 5;
    int k = bk & 3, b = bk >> 2;
    int d = threadIdx.x;

    float A2[Ns];
    const float* Ar = A_logs + (size_t)(k*DI + d) * Ns;
    #pragma unroll
    for (int n = 0; n < Ns; n++) A2[n] = -expf(Ar[n]) * LOG2E;
    bool geo = (A2[0] != 0.f);
    #pragma unroll
    for (int n = 1; n < Ns; n++)
        geo = geo && (fabsf(A2[n] - (float)(n+1)*A2[0]) <= 1e-4f * fabsf(A2[n]));

    int l0 = chunk * CLEN;
    size_t bkL = (size_t)bk * Ll;
    const float* dtp = g_dts + (bkL + l0) * DI + d;
    const float* xcb = g_xc + (size_t)b * Ll * DI + d;
    const float* cbase = g_c176 + (size_t)b * Ll * 176 + k * 44;
    size_t o = (((size_t)bk * NCHUNK + chunk) * DI + d) * Ns;

    if (geo){
        float A1 = A2[0];
        float rp = 1.f;
        ull h2[8] = {};
        for (int s = 0; s < CLEN; s++){
            int p = loc_of(k, l0 + s);
            float delta = dtp[0];
            float u = __ldg(xcb + (size_t)p * DI);
            float du = delta * u;
            float r = ex2f(delta * A1);
            ull pw[8]; powers16p(r, pw);
            const float* cp = cbase + (size_t)p * 176;
            ulonglong2 bA = *(const ulonglong2*)(cp + 12);
            ulonglong2 bB = *(const ulonglong2*)(cp + 16);
            ulonglong2 bC = *(const ulonglong2*)(cp + 20);
            ulonglong2 bD = *(const ulonglong2*)(cp + 24);
            ull dup = pk2(du, du);
            h2[0] = fma2(pw[0], h2[0], mul2(dup, bA.x));
            h2[1] = fma2(pw[1], h2[1], mul2(dup, bA.y));
            h2[2] = fma2(pw[2], h2[2], mul2(dup, bB.x));
            h2[3] = fma2(pw[3], h2[3], mul2(dup, bB.y));
            h2[4] = fma2(pw[4], h2[4], mul2(dup, bC.x));
            h2[5] = fma2(pw[5], h2[5], mul2(dup, bC.y));
            h2[6] = fma2(pw[6], h2[6], mul2(dup, bD.x));
            h2[7] = fma2(pw[7], h2[7], mul2(dup, bD.y));
            rp *= r;
            dtp += DI;
        }
        ull ap2[8]; powers16p(rp, ap2);
        ulonglong2* he = (ulonglong2*)(g_hend + o);
        ulonglong2* av = (ulonglong2*)(g_aprod + o);
        #pragma unroll
        for (int q = 0; q < 4; q++){
            ulonglong2 v1; v1.x = h2[2*q]; v1.y = h2[2*q+1]; he[q] = v1;
            ulonglong2 v2; v2.x = ap2[2*q]; v2.y = ap2[2*q+1]; av[q] = v2;
        }
    } else {
        float h[Ns], ap[Ns];
        #pragma unroll
        for (int n = 0; n < Ns; n++){ h[n] = 0.f; ap[n] = 1.f; }
        for (int s = 0; s < CLEN; s++){
            int p = loc_of(k, l0 + s);
            float delta = dtp[0];
            float u = __ldg(xcb + (size_t)p * DI);
            float du = delta * u;
            const float* cp = cbase + (size_t)p * 176;
            float Bv[Ns];
            *(float4*)&Bv[0]  = *(const float4*)(cp + 12);
            *(float4*)&Bv[4]  = *(const float4*)(cp + 16);
            *(float4*)&Bv[8]  = *(const float4*)(cp + 20);
            *(float4*)&Bv[12] = *(const float4*)(cp + 24);
            #pragma unroll
            for (int n = 0; n < Ns; n++){
                float dA = ex2f(delta * A2[n]);
                h[n] = fmaf(dA, h[n], du * Bv[n]);
                ap[n] *= dA;
            }
            dtp += DI;
        }
        float4* he = (float4*)(g_hend + o);
        float4* av = (float4*)(g_aprod + o);
        #pragma unroll
        for (int q = 0; q < 4; q++){
            he[q] = make_float4(h[4*q], h[4*q+1], h[4*q+2], h[4*q+3]);
            av[q] = make_float4(ap[4*q], ap[4*q+1], ap[4*q+2], ap[4*q+3]);
        }
    }
}

// pass B: sequential scan over chunks -> h_init per chunk
__global__ void k_scanB(){
    int gid = blockIdx.x * blockDim.x + threadIdx.x;
    int dn = gid % (DI*Ns);
    int bk = gid / (DI*Ns);
    size_t base = (size_t)bk * NCHUNK * DI * Ns + dn;
    float hr = 0.f;
    #pragma unroll 4
    for (int c = 0; c < NCHUNK; c++){
        size_t idx = base + (size_t)c * DI * Ns;
        g_hinit[idx] = hr;
        hr = g_aprod[idx] * hr + g_hend[idx];
    }
}

// pass C: replay with correct h_init, emit y = h.C + D*u
__global__ void __launch_bounds__(DI, 2) k_scanC(const float* __restrict__ A_logs,
                                                 const float* __restrict__ Ds){
    int blk = blockIdx.x;
    int chunk = blk & (NCHUNK - 1);
    int bk = blk >> 5;
    int k = bk & 3, b = bk >> 2;
    int d = threadIdx.x;

    float A2[Ns];
    const float* Ar = A_logs + (size_t)(k*DI + d) * Ns;
    #pragma unroll
    for (int n = 0; n < Ns; n++) A2[n] = -expf(Ar[n]) * LOG2E;
    bool geo = (A2[0] != 0.f);
    #pragma unroll
    for (int n = 1; n < Ns; n++)
        geo = geo && (fabsf(A2[n] - (float)(n+1)*A2[0]) <= 1e-4f * fabsf(A2[n]));
    float Dv = Ds[k*DI + d];

    int l0 = chunk * CLEN;
    size_t bkL = (size_t)bk * Ll;
    const float* dtp = g_dts + (bkL + l0) * DI + d;
    const float* xcb = g_xc + (size_t)b * Ll * DI + d;
    const float* cbase = g_c176 + (size_t)b * Ll * 176 + k * 44;
    float* yp = g_y + (bkL + l0) * DI + d;
    size_t o = (((size_t)bk * NCHUNK + chunk) * DI + d) * Ns;

    if (geo){
        float A1 = A2[0];
        ull h2[8];
        {
            const ulonglong2* hi = (const ulonglong2*)(g_hinit + o);
            #pragma unroll
            for (int q = 0; q < 4; q++){ ulonglong2 v = hi[q]; h2[2*q] = v.x; h2[2*q+1] = v.y; }
        }
        for (int s = 0; s < CLEN; s++){
            int p = loc_of(k, l0 + s);
            float delta = dtp[0];
            float u = __ldg(xcb + (size_t)p * DI);
            float du = delta * u;
            float r = ex2f(delta * A1);
            ull pw[8]; powers16p(r, pw);
            const float* cp = cbase + (size_t)p * 176;
            ulonglong2 bA = *(const ulonglong2*)(cp + 12);
            ulonglong2 bB = *(const ulonglong2*)(cp + 16);
            ulonglong2 bC = *(const ulonglong2*)(cp + 20);
            ulonglong2 bD = *(const ulonglong2*)(cp + 24);
            ulonglong2 cA = *(const ulonglong2*)(cp + 28);
            ulonglong2 cB = *(const ulonglong2*)(cp + 32);
            ulonglong2 cC = *(const ulonglong2*)(cp + 36);
            ulonglong2 cD = *(const ulonglong2*)(cp + 40);
            ull dup = pk2(du, du);
            h2[0] = fma2(pw[0], h2[0], mul2(dup, bA.x));
            h2[1] = fma2(pw[1], h2[1], mul2(dup, bA.y));
            h2[2] = fma2(pw[2], h2[2], mul2(dup, bB.x));
            h2[3] = fma2(pw[3], h2[3], mul2(dup, bB.y));
            h2[4] = fma2(pw[4], h2[4], mul2(dup, bC.x));
            h2[5] = fma2(pw[5], h2[5], mul2(dup, bC.y));
            h2[6] = fma2(pw[6], h2[6], mul2(dup, bD.x));
            h2[7] = fma2(pw[7], h2[7], mul2(dup, bD.y));
            ull acc2 = mul2(h2[0], cA.x);
            acc2 = fma2(h2[1], cA.y, acc2);
            acc2 = fma2(h2[2], cB.x, acc2);
            acc2 = fma2(h2[3], cB.y, acc2);
            acc2 = fma2(h2[4], cC.x, acc2);
            acc2 = fma2(h2[5], cC.y, acc2);
            acc2 = fma2(h2[6], cD.x, acc2);
            acc2 = fma2(h2[7], cD.y, acc2);
            float alo, ahi; upk2(acc2, alo, ahi);
            yp[0] = fmaf(Dv, u, alo + ahi);
            dtp += DI; yp += DI;
        }
    } else {
        float h[Ns];
        {
            const float4* hi = (const float4*)(g_hinit + o);
            #pragma unroll
            for (int q = 0; q < 4; q++){
                float4 v = hi[q];
                h[4*q] = v.x; h[4*q+1] = v.y; h[4*q+2] = v.z; h[4*q+3] = v.w;
            }
        }
        for (int s = 0; s < CLEN; s++){
            int p = loc_of(k, l0 + s);
            float delta = dtp[0];
            float u = __ldg(xcb + (size_t)p * DI);
            float du = delta * u;
            const float* cp = cbase + (size_t)p * 176;
            float acc = 0.f;
            #pragma unroll
            for (int q = 0; q < 4; q++){
                float4 bq = *(const float4*)(cp + 12 + 4*q);
                float4 cq = *(const float4*)(cp + 28 + 4*q);
                float dA0 = ex2f(delta * A2[4*q+0]);
                float dA1 = ex2f(delta * A2[4*q+1]);
                float dA2 = ex2f(delta * A2[4*q+2]);
                float dA3 = ex2f(delta * A2[4*q+3]);
                h[4*q+0] = fmaf(dA0, h[4*q+0], du * bq.x); acc = fmaf(h[4*q+0], cq.x, acc);
                h[4*q+1] = fmaf(dA1, h[4*q+1], du * bq.y); acc = fmaf(h[4*q+1], cq.y, acc);
                h[4*q+2] = fmaf(dA2, h[4*q+2], du * bq.z); acc = fmaf(h[4*q+2], cq.z, acc);
                h[4*q+3] = fmaf(dA3, h[4*q+3], du * bq.w); acc = fmaf(h[4*q+3], cq.w, acc);
            }
            yp[0] = fmaf(Dv, u, acc);
            dtp += DI; yp += DI;
        }
    }
}

// ---------------- merge 4 directions + LayerNorm + gate ----------------
__global__ void k_ln(const float* __restrict__ gam, const float* __restrict__ bet){
    int p = blockIdx.x % Ll;
    int b = blockIdx.x / Ll;
    int h = p / Ww, w = p % Ww;
    int l1 = w * Ww + h;
    int l2 = Ll - 1 - p;
    int l3 = Ll - 1 - l1;
    size_t bbase = (size_t)b * Kk * Ll;
    int t = threadIdx.x;
    float v[3];
    float s1 = 0.f, s2 = 0.f;
    #pragma unroll
    for (int j = 0; j < 3; j++){
        int d = t + j * 128;
        float y = g_y[(bbase + 0*Ll + p ) * DI + d]
                + g_y[(bbase + 1*Ll + l1) * DI + d]
                + g_y[(bbase + 2*Ll + l2) * DI + d]
                + g_y[(bbase + 3*Ll + l3) * DI + d];
        v[j] = y; s1 += y; s2 += y*y;
    }
    #pragma unroll
    for (int off = 16; off > 0; off >>= 1){
        s1 += __shfl_xor_sync(0xffffffffu, s1, off);
        s2 += __shfl_xor_sync(0xffffffffu, s2, off);
    }
    __shared__ float r1[4], r2[4];
    int warp = t >> 5, lane = t & 31;
    if (lane == 0){ r1[warp] = s1; r2[warp] = s2; }
    __syncthreads();
    float S1 = r1[0] + r1[1] + r1[2] + r1[3];
    float S2 = r2[0] + r2[1] + r2[2] + r2[3];
    float mu = S1 * (1.f / DI);
    float var = S2 * (1.f / DI) - mu * mu;
    float rstd = rsqrtf(var + 1e-5f);
    const float* zrow = g_xz + ((size_t)b*Ll + p) * (2*DI) + DI;
    float* grow = g_g + ((size_t)b*Ll + p) * DI;
    #pragma unroll
    for (int j = 0; j < 3; j++){
        int d = t + j * 128;
        float zn = zrow[d];
        float gate = zn * sigmoidf(zn);
        grow[d] = ((v[j] - mu) * rstd * gam[d] + bet[d]) * gate;
    }
}

// ---------------- launch ----------------
extern "C" void kernel_launch(void* const* d_in, const int* in_sizes, int n_in,
                              void* d_out, int out_size){
    const float* x      = (const float*)d_in[0];
    const float* in_w   = (const float*)d_in[1];
    const float* conv_w = (const float*)d_in[2];
    const float* conv_b = (const float*)d_in[3];
    const float* xproj  = (const float*)d_in[4];
    const float* dtw    = (const float*)d_in[5];
    const float* dtb    = (const float*)d_in[6];
    const float* Alog   = (const float*)d_in[7];
    const float* Ds     = (const float*)d_in[8];
    const float* gam    = (const float*)d_in[9];
    const float* bet    = (const float*)d_in[10];
    const float* outw   = (const float*)d_in[11];
    float* out = (float*)d_out;

    k_inproj <<<dim3((2*DI)/64, (Bb*Ll)/64), 256>>>(x, in_w);
    k_conv   <<<Bb*Ll, 128>>>(conv_w, conv_b);
    k_cproj  <<<dim3(3, (Bb*Ll)/64), 256>>>(xproj);
    k_dts    <<<dim3(Ll/32, Kk, Bb), DI>>>(dtw, dtb);
    k_scanA  <<<Bb*Kk*NCHUNK, DI>>>(Alog);
    k_scanB  <<<(Bb*Kk*DI*Ns)/256, 256>>>();
    k_scanC  <<<Bb*Kk*NCHUNK, DI>>>(Alog, Ds);
    k_ln     <<<Bb*Ll, 128>>>(gam, bet);
    k_outproj<<<dim3(DMo/64, (Bb*Ll)/64), 256>>>(outw, out);
}

// round 4
// speedup vs baseline: 1.5133x; 1.0200x over previous
#include <cuda_runtime.h>
#include <cstdint>

typedef unsigned long long ull;

#define Bb 2
#define Hh 48
#define Ww 48
#define DMo 192
#define Ns 16
#define DI 384
#define Rr 12
#define Kk 4
#define Ll (Hh*Ww)          // 2304
#define NCHUNK 36
#define CLEN (Ll/NCHUNK)    // 64
#define LOG2E 1.4426950408889634f
#define LN2 0.6931471805599453f

// ---------------- static device scratch ----------------
__device__ float g_xz  [(size_t)Bb*Ll*(2*DI)];      // in_proj output (b,l,768)
__device__ float g_xc  [(size_t)Bb*Ll*DI];          // conv+silu output (b,l,d)
__device__ float g_c176[(size_t)Bb*Ll*176];         // (b,p,176): per k: [k*44: 12 dt_r | +12: B(16) | +28: C(16)]
__device__ float g_dts [(size_t)Bb*Kk*Ll*DI];       // DELTA (post bias+softplus) (b,k,l,d)
__device__ float g_y   [(size_t)Bb*Kk*Ll*DI];       // per-direction scan output (b,k,l,d)
__device__ float g_g   [(size_t)Bb*Ll*DI];          // post-LN, gated (b,l,d)
__device__ float g_hend [(size_t)Bb*Kk*NCHUNK*DI*Ns];
__device__ float g_aprod[(size_t)Bb*Kk*NCHUNK*DI*Ns];
__device__ float g_hinit[(size_t)Bb*Kk*NCHUNK*DI*Ns];

// ---------------- helpers ----------------
__device__ __forceinline__ float ex2f(float x){ float y; asm("ex2.approx.f32 %0, %1;" : "=f"(y) : "f"(x)); return y; }
__device__ __forceinline__ float lg2f(float x){ float y; asm("lg2.approx.f32 %0, %1;" : "=f"(y) : "f"(x)); return y; }

__device__ __forceinline__ float softplus_fast(float x){
    if (x > 20.f) return x;
    float e = ex2f(x * LOG2E);
    return LN2 * lg2f(1.f + e);
}
__device__ __forceinline__ float sigmoidf(float x){
    return 1.f / (1.f + __expf(-x));
}

// packed fp32x2 ops (sm_103a; FFMA2 only reachable via PTX)
__device__ __forceinline__ ull pk2(float lo, float hi){
    ull r; asm("mov.b64 %0, {%1, %2};" : "=l"(r) : "r"(__float_as_uint(lo)), "r"(__float_as_uint(hi)));
    return r;
}
__device__ __forceinline__ void upk2(ull v, float& lo, float& hi){
    unsigned a, b; asm("mov.b64 {%0, %1}, %2;" : "=r"(a), "=r"(b) : "l"(v));
    lo = __uint_as_float(a); hi = __uint_as_float(b);
}
__device__ __forceinline__ ull fma2(ull a, ull b, ull c){
    ull d; asm("fma.rn.f32x2 %0, %1, %2, %3;" : "=l"(d) : "l"(a), "l"(b), "l"(c));
    return d;
}
__device__ __forceinline__ ull mul2(ull a, ull b){
    ull d; asm("mul.rn.f32x2 %0, %1, %2;" : "=l"(d) : "l"(a), "l"(b));
    return d;
}

// pair powers: p[i] = (r^(2i+1), r^(2i+2)), i=0..7  (squaring tree, short dep chain)
__device__ __forceinline__ void powers16p(float r, ull* p){
    float r2 = r*r, r4 = r2*r2, r8 = r4*r4;
    ull R2 = pk2(r2, r2), R4 = pk2(r4, r4), R8 = pk2(r8, r8);
    p[0] = pk2(r, r2);
    p[1] = mul2(p[0], R2);
    p[2] = mul2(p[0], R4);
    p[3] = mul2(p[1], R4);
    p[4] = mul2(p[0], R8);
    p[5] = mul2(p[1], R8);
    p[6] = mul2(p[2], R8);
    p[7] = mul2(p[3], R8);
}

// scan-step l of direction k reads raster location loc_of(k,l) (involution)
__device__ __forceinline__ int loc_of(int k, int l){
    int l2 = (k >= 2) ? (Ll - 1 - l) : l;
    if (k & 1){ int w = l2 / Ww; int h = l2 - w * Ww; return h * Ww + w; }
    return l2;
}

// ---------------- NT GEMM with FFMA2: C[M,Nrow] = A[M,K] * B[Nrow,K]^T ----------------
__device__ __forceinline__ void gemm_nt2(const float* __restrict__ A, const float* __restrict__ B,
                                         float* __restrict__ C, int K, int Nrow){
    __shared__ float As[16][68];
    __shared__ float Bs[16][68];
    int t  = threadIdx.x;
    int tx = t & 15, ty = t >> 4;
    int m0 = blockIdx.y * 64, n0 = blockIdx.x * 64;
    ull acc[4][2] = {};
    int r  = t >> 2;
    int kc = (t & 3) << 2;
    int brow = n0 + r; if (brow >= Nrow) brow = Nrow - 1;
    const float* Ap = A + (size_t)(m0 + r) * K + kc;
    const float* Bp = B + (size_t)brow * K + kc;
    for (int k0 = 0; k0 < K; k0 += 16){
        float4 av = *(const float4*)(Ap + k0);
        float4 bv = *(const float4*)(Bp + k0);
        As[kc+0][r] = av.x; As[kc+1][r] = av.y; As[kc+2][r] = av.z; As[kc+3][r] = av.w;
        Bs[kc+0][r] = bv.x; Bs[kc+1][r] = bv.y; Bs[kc+2][r] = bv.z; Bs[kc+3][r] = bv.w;
        __syncthreads();
        #pragma unroll
        for (int kk = 0; kk < 16; kk++){
            float4 a = *(const float4*)&As[kk][ty << 2];
            const ull* bp = (const ull*)&Bs[kk][tx << 2];
            ull b0 = bp[0], b1 = bp[1];
            ull a0 = pk2(a.x, a.x), a1 = pk2(a.y, a.y), a2 = pk2(a.z, a.z), a3 = pk2(a.w, a.w);
            acc[0][0] = fma2(a0, b0, acc[0][0]); acc[0][1] = fma2(a0, b1, acc[0][1]);
            acc[1][0] = fma2(a1, b0, acc[1][0]); acc[1][1] = fma2(a1, b1, acc[1][1]);
            acc[2][0] = fma2(a2, b0, acc[2][0]); acc[2][1] = fma2(a2, b1, acc[2][1]);
            acc[3][0] = fma2(a3, b0, acc[3][0]); acc[3][1] = fma2(a3, b1, acc[3][1]);
        }
        __syncthreads();
    }
    int nc = n0 + (tx << 2);
    if (nc < Nrow){
        #pragma unroll
        for (int i = 0; i < 4; i++){
            ulonglong2 v; v.x = acc[i][0]; v.y = acc[i][1];
            *(ulonglong2*)&C[(size_t)(m0 + ty*4 + i) * Nrow + nc] = v;
        }
    }
}

__global__ void k_inproj(const float* __restrict__ x, const float* __restrict__ w){
    gemm_nt2(x, w, g_xz, DMo, 2*DI);
}
__global__ void k_outproj(const float* __restrict__ w, float* __restrict__ out){
    gemm_nt2(g_g, w, out, DI, DMo);
}
__global__ void k_cproj(const float* __restrict__ xproj){
    gemm_nt2(g_xc, xproj, g_c176, DI, 176);
}

// ---------------- depthwise conv 3x3 + bias + SiLU (channel-last) ----------------
__global__ void k_conv(const float* __restrict__ cw, const float* __restrict__ cb){
    int p = blockIdx.x % Ll;
    int b = blockIdx.x / Ll;
    int h = p / Ww, w = p % Ww;
    const float* base = g_xz + (size_t)b * Ll * (2*DI);
    #pragma unroll
    for (int j = 0; j < 3; j++){
        int d = threadIdx.x + j * 128;
        float acc = cb[d];
        const float* wr = cw + d * 9;
        #pragma unroll
        for (int dh = -1; dh <= 1; dh++){
            int hh = h + dh;
            if ((unsigned)hh >= (unsigned)Hh) continue;
            #pragma unroll
            for (int dw = -1; dw <= 1; dw++){
                int ww2 = w + dw;
                if ((unsigned)ww2 >= (unsigned)Ww) continue;
                acc = fmaf(base[(size_t)(hh*Ww + ww2) * (2*DI) + d], wr[(dh+1)*3 + (dw+1)], acc);
            }
        }
        g_xc[((size_t)b*Ll + p) * DI + d] = acc * sigmoidf(acc);
    }
}

// ---------------- dt projection + bias + softplus (paired FFMA2) ----------------
// grid (Ll/64, K, B), 384 threads; 64 scan positions per block, 2 at a time.
__global__ void k_dts(const float* __restrict__ dtw, const float* __restrict__ dtb){
    __shared__ float sc[64][12];
    int l0 = blockIdx.x * 64;
    int k = blockIdx.y, b = blockIdx.z;
    int t = threadIdx.x;
    int d = t;
    size_t bkL = (size_t)(b*Kk + k) * Ll;
    const float* cbase = g_c176 + (size_t)b * Ll * 176 + k * 44;

    for (int i = t; i < 64*12; i += 384){
        int row = i / 12, col = i - row * 12;
        sc[row][col] = cbase[(size_t)loc_of(k, l0 + row) * 176 + col];
    }
    ull w2[Rr];
    #pragma unroll
    for (int r = 0; r < Rr; r++){
        float wv = dtw[((size_t)k*DI + d) * Rr + r];
        w2[r] = pk2(wv, wv);
    }
    float bias = dtb[k*DI + d];
    ull bias2 = pk2(bias, bias);
    __syncthreads();

    float* dp = g_dts + (bkL + l0) * DI + d;
    #pragma unroll 4
    for (int lp = 0; lp < 32; lp++){
        int l = 2*lp;
        float4 c0 = *(const float4*)&sc[l][0];
        float4 c1 = *(const float4*)&sc[l][4];
        float4 c2 = *(const float4*)&sc[l][8];
        float4 d0 = *(const float4*)&sc[l+1][0];
        float4 d1 = *(const float4*)&sc[l+1][4];
        float4 d2 = *(const float4*)&sc[l+1][8];
        ull acc = bias2;
        acc = fma2(w2[0],  pk2(c0.x, d0.x), acc);
        acc = fma2(w2[1],  pk2(c0.y, d0.y), acc);
        acc = fma2(w2[2],  pk2(c0.z, d0.z), acc);
        acc = fma2(w2[3],  pk2(c0.w, d0.w), acc);
        acc = fma2(w2[4],  pk2(c1.x, d1.x), acc);
        acc = fma2(w2[5],  pk2(c1.y, d1.y), acc);
        acc = fma2(w2[6],  pk2(c1.z, d1.z), acc);
        acc = fma2(w2[7],  pk2(c1.w, d1.w), acc);
        acc = fma2(w2[8],  pk2(c2.x, d2.x), acc);
        acc = fma2(w2[9],  pk2(c2.y, d2.y), acc);
        acc = fma2(w2[10], pk2(c2.z, d2.z), acc);
        acc = fma2(w2[11], pk2(c2.w, d2.w), acc);
        float a0, a1; upk2(acc, a0, a1);
        dp[(size_t)l * DI]     = softplus_fast(a0);
        dp[(size_t)(l+1) * DI] = softplus_fast(a1);
    }
}

// ---------------- selective scan, chunked (single resident wave: 288 blocks) ----------------
__global__ void __launch_bounds__(DI, 2) k_scanA(const float* __restrict__ A_logs){
    int blk = blockIdx.x;
    int chunk = blk % NCHUNK;
    int bk = blk / NCHUNK;
    int k = bk & 3, b = bk >> 2;
    int d = threadIdx.x;

    float A2[Ns];
    const float* Ar = A_logs + (size_t)(k*DI + d) * Ns;
    #pragma unroll
    for (int n = 0; n < Ns; n++) A2[n] = -expf(Ar[n]) * LOG2E;
    bool geo = (A2[0] != 0.f);
    #pragma unroll
    for (int n = 1; n < Ns; n++)
        geo = geo && (fabsf(A2[n] - (float)(n+1)*A2[0]) <= 1e-4f * fabsf(A2[n]));

    int l0 = chunk * CLEN;
    size_t bkL = (size_t)bk * Ll;
    const float* dtp = g_dts + (bkL + l0) * DI + d;
    const float* xcb = g_xc + (size_t)b * Ll * DI + d;
    const float* cbase = g_c176 + (size_t)b * Ll * 176 + k * 44;
    size_t o = (((size_t)bk * NCHUNK + chunk) * DI + d) * Ns;

    if (geo){
        float A1 = A2[0];
        float rp = 1.f;
        ull h2[8] = {};
        for (int s = 0; s < CLEN; s++){
            int p = loc_of(k, l0 + s);
            float delta = dtp[0];
            float u = __ldg(xcb + (size_t)p * DI);
            float du = delta * u;
            float r = ex2f(delta * A1);
            ull pw[8]; powers16p(r, pw);
            const float* cp = cbase + (size_t)p * 176;
            ulonglong2 bA = *(const ulonglong2*)(cp + 12);
            ulonglong2 bB = *(const ulonglong2*)(cp + 16);
            ulonglong2 bC = *(const ulonglong2*)(cp + 20);
            ulonglong2 bD = *(const ulonglong2*)(cp + 24);
            ull dup = pk2(du, du);
            h2[0] = fma2(pw[0], h2[0], mul2(dup, bA.x));
            h2[1] = fma2(pw[1], h2[1], mul2(dup, bA.y));
            h2[2] = fma2(pw[2], h2[2], mul2(dup, bB.x));
            h2[3] = fma2(pw[3], h2[3], mul2(dup, bB.y));
            h2[4] = fma2(pw[4], h2[4], mul2(dup, bC.x));
            h2[5] = fma2(pw[5], h2[5], mul2(dup, bC.y));
            h2[6] = fma2(pw[6], h2[6], mul2(dup, bD.x));
            h2[7] = fma2(pw[7], h2[7], mul2(dup, bD.y));
            rp *= r;
            dtp += DI;
        }
        ull ap2[8]; powers16p(rp, ap2);
        ulonglong2* he = (ulonglong2*)(g_hend + o);
        ulonglong2* av = (ulonglong2*)(g_aprod + o);
        #pragma unroll
        for (int q = 0; q < 4; q++){
            ulonglong2 v1; v1.x = h2[2*q]; v1.y = h2[2*q+1]; he[q] = v1;
            ulonglong2 v2; v2.x = ap2[2*q]; v2.y = ap2[2*q+1]; av[q] = v2;
        }
    } else {
        float h[Ns], ap[Ns];
        #pragma unroll
        for (int n = 0; n < Ns; n++){ h[n] = 0.f; ap[n] = 1.f; }
        for (int s = 0; s < CLEN; s++){
            int p = loc_of(k, l0 + s);
            float delta = dtp[0];
            float u = __ldg(xcb + (size_t)p * DI);
            float du = delta * u;
            const float* cp = cbase + (size_t)p * 176;
            float Bv[Ns];
            *(float4*)&Bv[0]  = *(const float4*)(cp + 12);
            *(float4*)&Bv[4]  = *(const float4*)(cp + 16);
            *(float4*)&Bv[8]  = *(const float4*)(cp + 20);
            *(float4*)&Bv[12] = *(const float4*)(cp + 24);
            #pragma unroll
            for (int n = 0; n < Ns; n++){
                float dA = ex2f(delta * A2[n]);
                h[n] = fmaf(dA, h[n], du * Bv[n]);
                ap[n] *= dA;
            }
            dtp += DI;
        }
        float4* he = (float4*)(g_hend + o);
        float4* av = (float4*)(g_aprod + o);
        #pragma unroll
        for (int q = 0; q < 4; q++){
            he[q] = make_float4(h[4*q], h[4*q+1], h[4*q+2], h[4*q+3]);
            av[q] = make_float4(ap[4*q], ap[4*q+1], ap[4*q+2], ap[4*q+3]);
        }
    }
}

// pass B: sequential scan over chunks -> h_init per chunk
__global__ void k_scanB(){
    int gid = blockIdx.x * blockDim.x + threadIdx.x;
    int dn = gid % (DI*Ns);
    int bk = gid / (DI*Ns);
    size_t base = (size_t)bk * NCHUNK * DI * Ns + dn;
    float hr = 0.f;
    #pragma unroll 4
    for (int c = 0; c < NCHUNK; c++){
        size_t idx = base + (size_t)c * DI * Ns;
        g_hinit[idx] = hr;
        hr = g_aprod[idx] * hr + g_hend[idx];
    }
}

// pass C: replay with correct h_init, emit y = h.C + D*u
__global__ void __launch_bounds__(DI, 2) k_scanC(const float* __restrict__ A_logs,
                                                 const float* __restrict__ Ds){
    int blk = blockIdx.x;
    int chunk = blk % NCHUNK;
    int bk = blk / NCHUNK;
    int k = bk & 3, b = bk >> 2;
    int d = threadIdx.x;

    float A2[Ns];
    const float* Ar = A_logs + (size_t)(k*DI + d) * Ns;
    #pragma unroll
    for (int n = 0; n < Ns; n++) A2[n] = -expf(Ar[n]) * LOG2E;
    bool geo = (A2[0] != 0.f);
    #pragma unroll
    for (int n = 1; n < Ns; n++)
        geo = geo && (fabsf(A2[n] - (float)(n+1)*A2[0]) <= 1e-4f * fabsf(A2[n]));
    float Dv = Ds[k*DI + d];

    int l0 = chunk * CLEN;
    size_t bkL = (size_t)bk * Ll;
    const float* dtp = g_dts + (bkL + l0) * DI + d;
    const float* xcb = g_xc + (size_t)b * Ll * DI + d;
    const float* cbase = g_c176 + (size_t)b * Ll * 176 + k * 44;
    float* yp = g_y + (bkL + l0) * DI + d;
    size_t o = (((size_t)bk * NCHUNK + chunk) * DI + d) * Ns;

    if (geo){
        float A1 = A2[0];
        ull h2[8];
        {
            const ulonglong2* hi = (const ulonglong2*)(g_hinit + o);
            #pragma unroll
            for (int q = 0; q < 4; q++){ ulonglong2 v = hi[q]; h2[2*q] = v.x; h2[2*q+1] = v.y; }
        }
        for (int s = 0; s < CLEN; s++){
            int p = loc_of(k, l0 + s);
            float delta = dtp[0];
            float u = __ldg(xcb + (size_t)p * DI);
            float du = delta * u;
            float r = ex2f(delta * A1);
            ull pw[8]; powers16p(r, pw);
            const float* cp = cbase + (size_t)p * 176;
            ulonglong2 bA = *(const ulonglong2*)(cp + 12);
            ulonglong2 bB = *(const ulonglong2*)(cp + 16);
            ulonglong2 bC = *(const ulonglong2*)(cp + 20);
            ulonglong2 bD = *(const ulonglong2*)(cp + 24);
            ulonglong2 cA = *(const ulonglong2*)(cp + 28);
            ulonglong2 cB = *(const ulonglong2*)(cp + 32);
            ulonglong2 cC = *(const ulonglong2*)(cp + 36);
            ulonglong2 cD = *(const ulonglong2*)(cp + 40);
            ull dup = pk2(du, du);
            h2[0] = fma2(pw[0], h2[0], mul2(dup, bA.x));
            h2[1] = fma2(pw[1], h2[1], mul2(dup, bA.y));
            h2[2] = fma2(pw[2], h2[2], mul2(dup, bB.x));
            h2[3] = fma2(pw[3], h2[3], mul2(dup, bB.y));
            h2[4] = fma2(pw[4], h2[4], mul2(dup, bC.x));
            h2[5] = fma2(pw[5], h2[5], mul2(dup, bC.y));
            h2[6] = fma2(pw[6], h2[6], mul2(dup, bD.x));
            h2[7] = fma2(pw[7], h2[7], mul2(dup, bD.y));
            ull acc2 = mul2(h2[0], cA.x);
            acc2 = fma2(h2[1], cA.y, acc2);
            acc2 = fma2(h2[2], cB.x, acc2);
            acc2 = fma2(h2[3], cB.y, acc2);
            acc2 = fma2(h2[4], cC.x, acc2);
            acc2 = fma2(h2[5], cC.y, acc2);
            acc2 = fma2(h2[6], cD.x, acc2);
            acc2 = fma2(h2[7], cD.y, acc2);
            float alo, ahi; upk2(acc2, alo, ahi);
            yp[0] = fmaf(Dv, u, alo + ahi);
            dtp += DI; yp += DI;
        }
    } else {
        float h[Ns];
        {
            const float4* hi = (const float4*)(g_hinit + o);
            #pragma unroll
            for (int q = 0; q < 4; q++){
                float4 v = hi[q];
                h[4*q] = v.x; h[4*q+1] = v.y; h[4*q+2] = v.z; h[4*q+3] = v.w;
            }
        }
        for (int s = 0; s < CLEN; s++){
            int p = loc_of(k, l0 + s);
            float delta = dtp[0];
            float u = __ldg(xcb + (size_t)p * DI);
            float du = delta * u;
            const float* cp = cbase + (size_t)p * 176;
            float acc = 0.f;
            #pragma unroll
            for (int q = 0; q < 4; q++){
                float4 bq = *(const float4*)(cp + 12 + 4*q);
                float4 cq = *(const float4*)(cp + 28 + 4*q);
                float dA0 = ex2f(delta * A2[4*q+0]);
                float dA1 = ex2f(delta * A2[4*q+1]);
                float dA2 = ex2f(delta * A2[4*q+2]);
                float dA3 = ex2f(delta * A2[4*q+3]);
                h[4*q+0] = fmaf(dA0, h[4*q+0], du * bq.x); acc = fmaf(h[4*q+0], cq.x, acc);
                h[4*q+1] = fmaf(dA1, h[4*q+1], du * bq.y); acc = fmaf(h[4*q+1], cq.y, acc);
                h[4*q+2] = fmaf(dA2, h[4*q+2], du * bq.z); acc = fmaf(h[4*q+2], cq.z, acc);
                h[4*q+3] = fmaf(dA3, h[4*q+3], du * bq.w); acc = fmaf(h[4*q+3], cq.w, acc);
            }
            yp[0] = fmaf(Dv, u, acc);
            dtp += DI; yp += DI;
        }
    }
}

// ---------------- merge 4 directions + LayerNorm + gate ----------------
__global__ void k_ln(const float* __restrict__ gam, const float* __restrict__ bet){
    int p = blockIdx.x % Ll;
    int b = blockIdx.x / Ll;
    int h = p / Ww, w = p % Ww;
    int l1 = w * Ww + h;
    int l2 = Ll - 1 - p;
    int l3 = Ll - 1 - l1;
    size_t bbase = (size_t)b * Kk * Ll;
    int t = threadIdx.x;
    float v[3];
    float s1 = 0.f, s2 = 0.f;
    #pragma unroll
    for (int j = 0; j < 3; j++){
        int d = t + j * 128;
        float y = g_y[(bbase + 0*Ll + p ) * DI + d]
                + g_y[(bbase + 1*Ll + l1) * DI + d]
                + g_y[(bbase + 2*Ll + l2) * DI + d]
                + g_y[(bbase + 3*Ll + l3) * DI + d];
        v[j] = y; s1 += y; s2 += y*y;
    }
    #pragma unroll
    for (int off = 16; off > 0; off >>= 1){
        s1 += __shfl_xor_sync(0xffffffffu, s1, off);
        s2 += __shfl_xor_sync(0xffffffffu, s2, off);
    }
    __shared__ float r1[4], r2[4];
    int warp = t >> 5, lane = t & 31;
    if (lane == 0){ r1[warp] = s1; r2[warp] = s2; }
    __syncthreads();
    float S1 = r1[0] + r1[1] + r1[2] + r1[3];
    float S2 = r2[0] + r2[1] + r2[2] + r2[3];
    float mu = S1 * (1.f / DI);
    float var = S2 * (1.f / DI) - mu * mu;
    float rstd = rsqrtf(var + 1e-5f);
    const float* zrow = g_xz + ((size_t)b*Ll + p) * (2*DI) + DI;
    float* grow = g_g + ((size_t)b*Ll + p) * DI;
    #pragma unroll
    for (int j = 0; j < 3; j++){
        int d = t + j * 128;
        float zn = zrow[d];
        float gate = zn * sigmoidf(zn);
        grow[d] = ((v[j] - mu) * rstd * gam[d] + bet[d]) * gate;
    }
}

// ---------------- launch ----------------
extern "C" void kernel_launch(void* const* d_in, const int* in_sizes, int n_in,
                              void* d_out, int out_size){
    const float* x      = (const float*)d_in[0];
    const float* in_w   = (const float*)d_in[1];
    const float* conv_w = (const float*)d_in[2];
    const float* conv_b = (const float*)d_in[3];
    const float* xproj  = (const float*)d_in[4];
    const float* dtw    = (const float*)d_in[5];
    const float* dtb    = (const float*)d_in[6];
    const float* Alog   = (const float*)d_in[7];
    const float* Ds     = (const float*)d_in[8];
    const float* gam    = (const float*)d_in[9];
    const float* bet    = (const float*)d_in[10];
    const float* outw   = (const float*)d_in[11];
    float* out = (float*)d_out;

    k_inproj <<<dim3((2*DI)/64, (Bb*Ll)/64), 256>>>(x, in_w);
    k_conv   <<<Bb*Ll, 128>>>(conv_w, conv_b);
    k_cproj  <<<dim3(3, (Bb*Ll)/64), 256>>>(xproj);
    k_dts    <<<dim3(Ll/64, Kk, Bb), DI>>>(dtw, dtb);
    k_scanA  <<<Bb*Kk*NCHUNK, DI>>>(Alog);
    k_scanB  <<<(Bb*Kk*DI*Ns)/256, 256>>>();
    k_scanC  <<<Bb*Kk*NCHUNK, DI>>>(Alog, Ds);
    k_ln     <<<Bb*Ll, 128>>>(gam, bet);
    k_outproj<<<dim3(DMo/64, (Bb*Ll)/64), 256>>>(outw, out);
}